// round 15
// baseline (speedup 1.0000x reference)
#include <cuda_runtime.h>
#include <cstdint>

constexpr int B_ = 64, C_ = 512, NE_ = 80, NI_ = 20, E_ = 512;
#define DTC 0.1f

// bf16 stage per CTA: A [64 x 32] + W-half [40 x 32], row stride 80 bytes.
constexpr int LDB     = 80;
constexpr int A_BYTES = 64 * LDB;           // 5120
constexpr int W_BYTES = 40 * LDB;           // 3200
constexpr int STAGE_B = A_BYTES + W_BYTES;  // 8320
constexpr int NSTAGE  = 3;
constexpr int LDWEI   = 96;                 // W_ei f32 rows, cols 80..95 zero
constexpr int WEI_OFF = NSTAGE * STAGE_B;             // 24960
constexpr int SMEM_BYTES = WEI_OFF + 20 * LDWEI * 4;  // 32640 -> 4+ CTAs/SM

constexpr size_t OFF_RI = (size_t)B_ * C_ * NE_;
constexpr size_t OFF_VE = OFF_RI + (size_t)B_ * C_ * NI_;
constexpr size_t OFF_VI = OFF_VE + (size_t)B_ * C_ * NE_;

__device__ __forceinline__ uint32_t s2u(const void* p) {
    uint32_t a;
    asm("{ .reg .u64 t; cvta.to.shared.u64 t, %1; cvt.u32.u64 %0, t; }" : "=r"(a) : "l"(p));
    return a;
}
__device__ __forceinline__ uint32_t bfx2(float2 f) {
    uint32_t r;
    asm("cvt.rn.bf16x2.f32 %0, %1, %2;" : "=r"(r) : "f"(f.y), "f"(f.x));
    return r;
}
__device__ __forceinline__ void sts_bf(uint32_t addr, float4 v) {
    uint32_t lo = bfx2(make_float2(v.x, v.y));
    uint32_t hi = bfx2(make_float2(v.z, v.w));
    asm volatile("st.shared.v2.b32 [%0], {%1,%2};" :: "r"(addr), "r"(lo), "r"(hi));
}
__device__ __forceinline__ void ldsm4(uint32_t r[4], uint32_t addr) {
    asm volatile("ldmatrix.sync.aligned.m8n8.x4.shared.b16 {%0,%1,%2,%3}, [%4];"
        : "=r"(r[0]), "=r"(r[1]), "=r"(r[2]), "=r"(r[3]) : "r"(addr));
}
__device__ __forceinline__ void mma16(float d[4], uint32_t a0, uint32_t a1,
                                      uint32_t a2, uint32_t a3,
                                      uint32_t b0, uint32_t b1) {
    asm("mma.sync.aligned.m16n8k16.row.col.f32.bf16.bf16.f32 "
        "{%0,%1,%2,%3}, {%4,%5,%6,%7}, {%8,%9}, {%0,%1,%2,%3};"
        : "+f"(d[0]), "+f"(d[1]), "+f"(d[2]), "+f"(d[3])
        : "r"(a0), "r"(a1), "r"(a2), "r"(a3), "r"(b0), "r"(b1));
}

// register staging: 4 A float4s (idx = t+128i, i<4) + 3 W float4s (idx<320)
struct St { float4 a[4]; float4 wv[3]; };

// chunk table:
// ci 0-15 : I_ext k0=ci*32 (A=thal_inc, W=input_proj rows nh*40+0..39)
// ci 16-18: I_fb  k0=(ci-16)*32 (A=l23_fb, W=feedback_proj; cols>=80 zero)
// ci 19-21: I_ee  k0=(ci-19)*32 (A=r_e, W=W_ee; cols>=80 zero) + I_ei (nh==0)
// ci 22   : I_ie  K=20 pad 32 (A=r_i negated at cvt, W=W_ie)
__device__ __forceinline__ void load_chunk(
    int ci, int c, int wrow0, int t, St& s,
    const float* thal_inc, const float* l23_fb, const float* r_e,
    const float* r_i, const float* input_proj, const float* feedback_proj,
    const float* W_ee, const float* W_ie) {
    const float4 z = make_float4(0.f, 0.f, 0.f, 0.f);
    if (ci < 16) {
        const int k0 = ci * 32;
#pragma unroll
        for (int i = 0; i < 4; i++) {
            int idx = t + 128 * i, row = idx >> 3, g = idx & 7;
            s.a[i] = __ldg((const float4*)(thal_inc + ((size_t)row * C_ + c) * E_ + k0 + g * 4));
        }
#pragma unroll
        for (int i = 0; i < 3; i++) {
            int idx = t + 128 * i;
            if (idx < 320) {
                int row = idx >> 3, g = idx & 7;
                s.wv[i] = __ldg((const float4*)(input_proj + ((size_t)c * NE_ + wrow0 + row) * E_ + k0 + g * 4));
            }
        }
    } else if (ci < 22) {
        const bool isB = ci < 19;
        const int k0 = (ci - (isB ? 16 : 19)) * 32;
        const float* Ap = isB ? l23_fb : r_e;
        const float* Wp = isB ? feedback_proj : W_ee;
#pragma unroll
        for (int i = 0; i < 4; i++) {
            int idx = t + 128 * i, row = idx >> 3, g = idx & 7, col = k0 + g * 4;
            s.a[i] = (col < NE_) ? __ldg((const float4*)(Ap + ((size_t)row * C_ + c) * NE_ + col)) : z;
        }
#pragma unroll
        for (int i = 0; i < 3; i++) {
            int idx = t + 128 * i;
            if (idx < 320) {
                int row = idx >> 3, g = idx & 7, col = k0 + g * 4;
                s.wv[i] = (col < NE_) ? __ldg((const float4*)(Wp + ((size_t)c * NE_ + wrow0 + row) * NE_ + col)) : z;
            }
        }
    } else {
#pragma unroll
        for (int i = 0; i < 4; i++) {
            int idx = t + 128 * i, row = idx >> 3, g = idx & 7;
            s.a[i] = (g < 5) ? __ldg((const float4*)(r_i + ((size_t)row * C_ + c) * NI_ + g * 4)) : z;
        }
#pragma unroll
        for (int i = 0; i < 3; i++) {
            int idx = t + 128 * i;
            if (idx < 320) {
                int row = idx >> 3, g = idx & 7;
                s.wv[i] = (g < 5) ? __ldg((const float4*)(W_ie + ((size_t)c * NE_ + wrow0 + row) * NI_ + g * 4)) : z;
            }
        }
    }
}

__device__ __forceinline__ void cvt_sts(int ci, int t, const St& s,
                                        uint32_t smb, const float* thal) {
    const uint32_t base = smb + (ci % NSTAGE) * STAGE_B;
#pragma unroll
    for (int i = 0; i < 4; i++) {
        int idx = t + 128 * i, row = idx >> 3, g = idx & 7;
        float4 a = s.a[i];
        if (ci < 16) {   // fold broadcast thal (L2-hot) before conversion
            float4 th = __ldg((const float4*)(thal + (size_t)row * E_ + ci * 32 + g * 4));
            a.x += th.x; a.y += th.y; a.z += th.z; a.w += th.w;
        } else if (ci == 22) {
            a.x = -a.x; a.y = -a.y; a.z = -a.z; a.w = -a.w;
        }
        sts_bf(base + row * LDB + g * 8, a);
    }
#pragma unroll
    for (int i = 0; i < 3; i++) {
        int idx = t + 128 * i;
        if (idx < 320) {
            int row = idx >> 3, g = idx & 7;
            sts_bf(base + A_BYTES + row * LDB + g * 8, s.wv[i]);
        }
    }
}

__global__ void __launch_bounds__(128, 4)
ei_half(const float* __restrict__ thal, const float* __restrict__ thal_inc,
        const float* __restrict__ l23_fb, const float* __restrict__ r_e,
        const float* __restrict__ r_i, const float* __restrict__ e_v,
        const float* __restrict__ i_v, const float* __restrict__ input_proj,
        const float* __restrict__ feedback_proj, const float* __restrict__ W_ee,
        const float* __restrict__ W_ei, const float* __restrict__ W_ie,
        float* __restrict__ out) {
    extern __shared__ char smp[];
    const uint32_t smb = s2u(smp);
    const int t = threadIdx.x;
    const int c  = blockIdx.x >> 1;        // column
    const int nh = blockIdx.x & 1;         // N-half: E-cols [nh*40, nh*40+40)
    const int wrow0 = nh * 40;
    const int wm = t >> 5, lane = t & 31;
    const int m0 = wm * 16, lm = lane >> 2, lc = lane & 3;

    float accE[5][4], accI[3][4];
#pragma unroll
    for (int j = 0; j < 5; j++)
#pragma unroll
        for (int q = 0; q < 4; q++) accE[j][q] = 0.f;
#pragma unroll
    for (int j = 0; j < 3; j++)
#pragma unroll
        for (int q = 0; q < 4; q++) accI[j][q] = 0.f;

    // ---- persistent W_ei f32 buffer (nh==0 only; 20 rows x 96, cols>=80 zero)
    if (nh == 0) {
        for (int idx = t; idx < 480; idx += 128) {
            int row = idx / 24, g = idx % 24;
            float4 v = make_float4(0.f, 0.f, 0.f, 0.f);
            if (g < 20) v = __ldg((const float4*)(W_ei + ((size_t)c * NI_ + row) * NE_ + g * 4));
            *(float4*)(smp + WEI_OFF + (row * LDWEI + g * 4) * 4) = v;
        }
    }
    const float* Wei = (const float*)(smp + WEI_OFF);
    const bool wiv2 = (lm < 4);

    // ---- ldmatrix addresses (slot-relative) ----
    const uint32_t a_off = (uint32_t)((m0 + (lane & 7) + ((lane >> 3) & 1) * 8) * LDB
                                      + (lane >> 4) * 16);
    const uint32_t w_off = (uint32_t)(A_BYTES + (lane & 7) * LDB + (lane >> 3) * 16);

    auto compute = [&](int ci) {
        const uint32_t base = smb + (ci % NSTAGE) * STAGE_B;
        uint32_t Ak0[4], Ak1[4];
        ldsm4(Ak0, base + a_off);
        ldsm4(Ak1, base + a_off + 32);
#pragma unroll
        for (int j = 0; j < 5; j++) {
            uint32_t Bf[4];
            ldsm4(Bf, base + w_off + (uint32_t)(j * 8 * LDB));
            mma16(accE[j], Ak0[0], Ak0[1], Ak0[2], Ak0[3], Bf[0], Bf[1]);
            mma16(accE[j], Ak1[0], Ak1[1], Ak1[2], Ak1[3], Bf[2], Bf[3]);
        }
        if (ci >= 19 && ci <= 21 && nh == 0) {
            const int kei0 = (ci - 19) * 32;
            const float2 z = make_float2(0.f, 0.f);
#pragma unroll
            for (int j = 0; j < 3; j++) {
                const bool v = (j < 2) || wiv2;
                const float* wp = Wei + (j * 8 + (v ? lm : 0)) * LDWEI + kei0 + 2 * lc;
                uint32_t b0 = bfx2(v ? *(const float2*)(wp) : z);
                uint32_t b1 = bfx2(v ? *(const float2*)(wp + 8) : z);
                mma16(accI[j], Ak0[0], Ak0[1], Ak0[2], Ak0[3], b0, b1);
                uint32_t b2 = bfx2(v ? *(const float2*)(wp + 16) : z);
                uint32_t b3 = bfx2(v ? *(const float2*)(wp + 24) : z);
                mma16(accI[j], Ak1[0], Ak1[1], Ak1[2], Ak1[3], b2, b3);
            }
        }
    };

    // ---- software pipeline: LDG(ci+2) | compute(ci) | cvt+STS(ci+1) ----
    St sA, sB;
    load_chunk(0, c, wrow0, t, sA, thal_inc, l23_fb, r_e, r_i, input_proj, feedback_proj, W_ee, W_ie);
    load_chunk(1, c, wrow0, t, sB, thal_inc, l23_fb, r_e, r_i, input_proj, feedback_proj, W_ee, W_ie);
    cvt_sts(0, t, sA, smb, thal);
    __syncthreads();

#pragma unroll 1
    for (int ci = 0; ci < 23; ci += 2) {
        if (ci + 2 < 23)
            load_chunk(ci + 2, c, wrow0, t, sA, thal_inc, l23_fb, r_e, r_i,
                       input_proj, feedback_proj, W_ee, W_ie);
        compute(ci);
        if (ci + 1 < 23) cvt_sts(ci + 1, t, sB, smb, thal);
        __syncthreads();
        if (ci + 1 < 23) {
            if (ci + 3 < 23)
                load_chunk(ci + 3, c, wrow0, t, sB, thal_inc, l23_fb, r_e, r_i,
                           input_proj, feedback_proj, W_ee, W_ie);
            compute(ci + 1);
            if (ci + 2 < 23) cvt_sts(ci + 2, t, sA, smb, thal);
            __syncthreads();
        }
    }
    // NOTE: chunk 22 is computed inside the final loop iteration (ci == 22).
    // R14's bug was an extra compute(22) here, double-counting I_ie.

    // ---------------- epilogue: leaky integration + relu ----------------
    const int r0 = m0 + lm, r1 = r0 + 8;
#pragma unroll
    for (int j = 0; j < 5; j++) {
        const int col = wrow0 + j * 8 + 2 * lc;
        const size_t i0 = ((size_t)r0 * C_ + c) * NE_ + col;
        const size_t i1 = ((size_t)r1 * C_ + c) * NE_ + col;
        float2 ev0 = *(const float2*)(e_v + i0);
        float2 ev1 = *(const float2*)(e_v + i1);
        float v0x = ev0.x + DTC * (accE[j][0] - ev0.x);
        float v0y = ev0.y + DTC * (accE[j][1] - ev0.y);
        float v1x = ev1.x + DTC * (accE[j][2] - ev1.x);
        float v1y = ev1.y + DTC * (accE[j][3] - ev1.y);
        *(float2*)(out + i0)          = make_float2(fmaxf(v0x, 0.f), fmaxf(v0y, 0.f));
        *(float2*)(out + i1)          = make_float2(fmaxf(v1x, 0.f), fmaxf(v1y, 0.f));
        *(float2*)(out + OFF_VE + i0) = make_float2(v0x, v0y);
        *(float2*)(out + OFF_VE + i1) = make_float2(v1x, v1y);
    }
    if (nh == 0) {
#pragma unroll
        for (int j = 0; j < 3; j++) {
            const int col = j * 8 + 2 * lc;
            if (col < NI_) {
                const size_t i0 = ((size_t)r0 * C_ + c) * NI_ + col;
                const size_t i1 = ((size_t)r1 * C_ + c) * NI_ + col;
                float2 iv0 = *(const float2*)(i_v + i0);
                float2 iv1 = *(const float2*)(i_v + i1);
                float v0x = iv0.x + DTC * (accI[j][0] - iv0.x);
                float v0y = iv0.y + DTC * (accI[j][1] - iv0.y);
                float v1x = iv1.x + DTC * (accI[j][2] - iv1.x);
                float v1y = iv1.y + DTC * (accI[j][3] - iv1.y);
                *(float2*)(out + OFF_RI + i0) = make_float2(fmaxf(v0x, 0.f), fmaxf(v0y, 0.f));
                *(float2*)(out + OFF_RI + i1) = make_float2(fmaxf(v1x, 0.f), fmaxf(v1y, 0.f));
                *(float2*)(out + OFF_VI + i0) = make_float2(v0x, v0y);
                *(float2*)(out + OFF_VI + i1) = make_float2(v1x, v1y);
            }
        }
    }
}

extern "C" void kernel_launch(void* const* d_in, const int* in_sizes, int n_in,
                              void* d_out, int out_size) {
    (void)in_sizes; (void)n_in; (void)out_size;
    cudaFuncSetAttribute(ei_half, cudaFuncAttributeMaxDynamicSharedMemorySize,
                         SMEM_BYTES);
    ei_half<<<2 * C_, 128, SMEM_BYTES>>>(
        (const float*)d_in[0],   // thal
        (const float*)d_in[1],   // thal_increments
        (const float*)d_in[2],   // l23_fb
        (const float*)d_in[3],   // r_e
        (const float*)d_in[4],   // r_i
        (const float*)d_in[5],   // e_v
        (const float*)d_in[6],   // i_v
        (const float*)d_in[7],   // input_proj
        (const float*)d_in[8],   // feedback_proj
        (const float*)d_in[9],   // W_ee
        (const float*)d_in[10],  // W_ei
        (const float*)d_in[11],  // W_ie
        (float*)d_out);
}

// round 16
// speedup vs baseline: 1.4605x; 1.4605x over previous
#include <cuda_runtime.h>
#include <cstdint>

constexpr int B_ = 64, C_ = 512, NE_ = 80, NI_ = 20, E_ = 512;
#define DTC 0.1f

// bf16 stage: A [64 x 32] + W [80 x 32], row stride 80 bytes (16B-aligned,
// r*80 mod 128 distinct over 8 rows -> conflict-free ldmatrix).
constexpr int LDB     = 80;                 // bytes per bf16 row
constexpr int A_BYTES = 64 * LDB;           // 5120
constexpr int W_BYTES = 80 * LDB;           // 6400
constexpr int STAGE_B = A_BYTES + W_BYTES;  // 11520
constexpr int NSTAGE  = 3;
// persistent W_ei f32 buffer: 20 rows x 96 floats (cols 80..95 zeroed so the
// ci==21 k-window 64..95 never reads past the row)
constexpr int LDWEI   = 96;
constexpr int WEI_OFF = NSTAGE * STAGE_B;             // 34560 B
constexpr int SMEM_BYTES = WEI_OFF + 20 * LDWEI * 4;  // 42240 B

constexpr size_t OFF_RI = (size_t)B_ * C_ * NE_;
constexpr size_t OFF_VE = OFF_RI + (size_t)B_ * C_ * NI_;
constexpr size_t OFF_VI = OFF_VE + (size_t)B_ * C_ * NE_;

// ---------------- helpers ----------------
__device__ __forceinline__ uint32_t s2u(const void* p) {
    uint32_t a;
    asm("{ .reg .u64 t; cvta.to.shared.u64 t, %1; cvt.u32.u64 %0, t; }" : "=r"(a) : "l"(p));
    return a;
}
__device__ __forceinline__ uint32_t bfx2(float2 f) {
    uint32_t r;
    asm("cvt.rn.bf16x2.f32 %0, %1, %2;" : "=r"(r) : "f"(f.y), "f"(f.x));
    return r;
}
__device__ __forceinline__ void sts_bf(uint32_t addr, float4 v) {
    uint32_t lo = bfx2(make_float2(v.x, v.y));
    uint32_t hi = bfx2(make_float2(v.z, v.w));
    asm volatile("st.shared.v2.b32 [%0], {%1,%2};" :: "r"(addr), "r"(lo), "r"(hi));
}
__device__ __forceinline__ void ldsm4(uint32_t r[4], uint32_t addr) {
    asm volatile("ldmatrix.sync.aligned.m8n8.x4.shared.b16 {%0,%1,%2,%3}, [%4];"
        : "=r"(r[0]), "=r"(r[1]), "=r"(r[2]), "=r"(r[3]) : "r"(addr));
}
__device__ __forceinline__ void mma16(float d[4], uint32_t a0, uint32_t a1,
                                      uint32_t a2, uint32_t a3,
                                      uint32_t b0, uint32_t b1) {
    asm("mma.sync.aligned.m16n8k16.row.col.f32.bf16.bf16.f32 "
        "{%0,%1,%2,%3}, {%4,%5,%6,%7}, {%8,%9}, {%0,%1,%2,%3};"
        : "+f"(d[0]), "+f"(d[1]), "+f"(d[2]), "+f"(d[3])
        : "r"(a0), "r"(a1), "r"(a2), "r"(a3), "r"(b0), "r"(b1));
}

// register-staged chunk: 2 A float4 groups + 3 W float4 groups per thread
struct St { float4 a0, a1, w0, w1, w2; };

// chunk table:
// ci 0-15 : I_ext k0=ci*32 (A=thal_inc + thal folded at load, W=input_proj)
// ci 16-18: I_fb  k0=(ci-16)*32 (A=l23_fb, W=feedback_proj; k>=80 zero)
// ci 19-21: I_ee  k0=(ci-19)*32 (A=r_e, W=W_ee; k>=80 zero) + I_ei via Wei
// ci 22   : I_ie  K=20 pad 32 (A=r_i negated at cvt, W=W_ie)
__device__ __forceinline__ void load_chunk(
    int ci, int c, int t, St& s,
    const float* thal, const float* thal_inc, const float* l23_fb,
    const float* r_e, const float* r_i, const float* input_proj,
    const float* feedback_proj, const float* W_ee, const float* W_ie) {
    const int rA = t >> 3, g = t & 7;
    const float4 z = make_float4(0.f, 0.f, 0.f, 0.f);
    if (ci < 16) {
        const int k0 = ci * 32 + g * 4;
        // thal fold at load time: LDGs batched here, FADDs sink into the
        // compute shadow (s consumed only after compute(ci)).
        float4 a0 = __ldg((const float4*)(thal_inc + ((size_t)rA * C_ + c) * E_ + k0));
        float4 t0 = __ldg((const float4*)(thal + (size_t)rA * E_ + k0));
        float4 a1 = __ldg((const float4*)(thal_inc + ((size_t)(rA + 32) * C_ + c) * E_ + k0));
        float4 t1 = __ldg((const float4*)(thal + (size_t)(rA + 32) * E_ + k0));
        s.w0 = __ldg((const float4*)(input_proj + ((size_t)c * NE_ + rA) * E_ + k0));
        s.w1 = __ldg((const float4*)(input_proj + ((size_t)c * NE_ + rA + 32) * E_ + k0));
        s.w2 = (t < 128) ? __ldg((const float4*)(input_proj + ((size_t)c * NE_ + rA + 64) * E_ + k0)) : z;
        a0.x += t0.x; a0.y += t0.y; a0.z += t0.z; a0.w += t0.w;
        a1.x += t1.x; a1.y += t1.y; a1.z += t1.z; a1.w += t1.w;
        s.a0 = a0; s.a1 = a1;
    } else if (ci < 22) {
        const bool isB = ci < 19;
        const int col = (ci - (isB ? 16 : 19)) * 32 + g * 4;
        const float* Ap = isB ? l23_fb : r_e;
        const float* Wp = isB ? feedback_proj : W_ee;
        const bool v = col < NE_;
        s.a0 = v ? __ldg((const float4*)(Ap + ((size_t)rA * C_ + c) * NE_ + col)) : z;
        s.a1 = v ? __ldg((const float4*)(Ap + ((size_t)(rA + 32) * C_ + c) * NE_ + col)) : z;
        s.w0 = v ? __ldg((const float4*)(Wp + ((size_t)c * NE_ + rA) * NE_ + col)) : z;
        s.w1 = v ? __ldg((const float4*)(Wp + ((size_t)c * NE_ + rA + 32) * NE_ + col)) : z;
        s.w2 = (v && t < 128) ? __ldg((const float4*)(Wp + ((size_t)c * NE_ + rA + 64) * NE_ + col)) : z;
    } else {
        const int col = g * 4;
        const bool v = col < NI_;
        s.a0 = v ? __ldg((const float4*)(r_i + ((size_t)rA * C_ + c) * NI_ + col)) : z;
        s.a1 = v ? __ldg((const float4*)(r_i + ((size_t)(rA + 32) * C_ + c) * NI_ + col)) : z;
        s.w0 = v ? __ldg((const float4*)(W_ie + ((size_t)c * NE_ + rA) * NI_ + col)) : z;
        s.w1 = v ? __ldg((const float4*)(W_ie + ((size_t)c * NE_ + rA + 32) * NI_ + col)) : z;
        s.w2 = (v && t < 128) ? __ldg((const float4*)(W_ie + ((size_t)c * NE_ + rA + 64) * NI_ + col)) : z;
    }
}

// pure register -> smem conversion pass: no memory dependencies.
__device__ __forceinline__ void cvt_sts(int ci, int t, const St& s, uint32_t smb) {
    const uint32_t base = smb + (ci % NSTAGE) * STAGE_B;
    const int rA = t >> 3, g = t & 7;
    float4 a0 = s.a0, a1 = s.a1;
    if (ci == 22) {   // negate A for inhibitory current
        a0.x = -a0.x; a0.y = -a0.y; a0.z = -a0.z; a0.w = -a0.w;
        a1.x = -a1.x; a1.y = -a1.y; a1.z = -a1.z; a1.w = -a1.w;
    }
    sts_bf(base + rA * LDB + g * 8, a0);
    sts_bf(base + (rA + 32) * LDB + g * 8, a1);
    const uint32_t wb = base + A_BYTES;
    sts_bf(wb + rA * LDB + g * 8, s.w0);
    sts_bf(wb + (rA + 32) * LDB + g * 8, s.w1);
    if (t < 128) sts_bf(wb + (rA + 64) * LDB + g * 8, s.w2);
}

__global__ void __launch_bounds__(256, 2)
ei_ldsm(const float* __restrict__ thal, const float* __restrict__ thal_inc,
        const float* __restrict__ l23_fb, const float* __restrict__ r_e,
        const float* __restrict__ r_i, const float* __restrict__ e_v,
        const float* __restrict__ i_v, const float* __restrict__ input_proj,
        const float* __restrict__ feedback_proj, const float* __restrict__ W_ee,
        const float* __restrict__ W_ei, const float* __restrict__ W_ie,
        float* __restrict__ out) {
    extern __shared__ char smp[];
    const uint32_t smb = s2u(smp);
    const int t = threadIdx.x, c = blockIdx.x;
    const int w = t >> 5, lane = t & 31;
    const int wm = w >> 1, wn = w & 1;
    const int m0 = wm * 16, lm = lane >> 2, lc = lane & 3;

    float accE[5][4], accI[3][4];
#pragma unroll
    for (int j = 0; j < 5; j++)
#pragma unroll
        for (int q = 0; q < 4; q++) accE[j][q] = 0.f;
#pragma unroll
    for (int j = 0; j < 3; j++)
#pragma unroll
        for (int q = 0; q < 4; q++) accI[j][q] = 0.f;

    // ---- persistent W_ei f32 buffer (20 rows x 96, cols >=80 zero) ----
    for (int idx = t; idx < 480; idx += 256) {
        int row = idx / 24, g = idx % 24;
        float4 v = make_float4(0.f, 0.f, 0.f, 0.f);
        if (g < 20) v = __ldg((const float4*)(W_ei + ((size_t)c * NI_ + row) * NE_ + g * 4));
        *(float4*)(smp + WEI_OFF + (row * LDWEI + g * 4) * 4) = v;
    }
    const float* Wei = (const float*)(smp + WEI_OFF);
    const bool wiv2 = (lm < 4);

    // ---- LDSM/fragment addresses (per lane, slot-relative) ----
    const uint32_t a_off = (uint32_t)((m0 + (lane & 7) + ((lane >> 3) & 1) * 8) * LDB
                                      + (lane >> 4) * 16);
    const uint32_t w_off = (uint32_t)(A_BYTES + (wn * 40 + (lane & 7)) * LDB
                                      + (lane >> 3) * 16);

    auto compute = [&](int ci) {
        const uint32_t base = smb + (ci % NSTAGE) * STAGE_B;
        uint32_t Ak0[4], Ak1[4];
        ldsm4(Ak0, base + a_off);
        ldsm4(Ak1, base + a_off + 32);
#pragma unroll
        for (int j = 0; j < 5; j++) {
            uint32_t Bf[4];
            ldsm4(Bf, base + w_off + (uint32_t)(j * 8 * LDB));
            mma16(accE[j], Ak0[0], Ak0[1], Ak0[2], Ak0[3], Bf[0], Bf[1]);
            mma16(accE[j], Ak1[0], Ak1[1], Ak1[2], Ak1[3], Bf[2], Bf[3]);
        }
        if (ci >= 19 && ci <= 21 && wn == 0) {
            const int kei0 = (ci - 19) * 32;
            const float2 z = make_float2(0.f, 0.f);
#pragma unroll
            for (int j = 0; j < 3; j++) {
                const bool v = (j < 2) || wiv2;
                const float* wp = Wei + (j * 8 + (v ? lm : 0)) * LDWEI + kei0 + 2 * lc;
                uint32_t b0 = bfx2(v ? *(const float2*)(wp) : z);
                uint32_t b1 = bfx2(v ? *(const float2*)(wp + 8) : z);
                mma16(accI[j], Ak0[0], Ak0[1], Ak0[2], Ak0[3], b0, b1);
                uint32_t b2 = bfx2(v ? *(const float2*)(wp + 16) : z);
                uint32_t b3 = bfx2(v ? *(const float2*)(wp + 24) : z);
                mma16(accI[j], Ak1[0], Ak1[1], Ak1[2], Ak1[3], b2, b3);
            }
        }
    };

    // ---- software pipeline: LDG(ci+2) | compute(ci) | cvt+STS(ci+1) ----
    St sA, sB;
    load_chunk(0, c, t, sA, thal, thal_inc, l23_fb, r_e, r_i, input_proj, feedback_proj, W_ee, W_ie);
    load_chunk(1, c, t, sB, thal, thal_inc, l23_fb, r_e, r_i, input_proj, feedback_proj, W_ee, W_ie);
    cvt_sts(0, t, sA, smb);
    __syncthreads();

#pragma unroll 1
    for (int ci = 0; ci < 23; ci += 2) {
        if (ci + 2 < 23)
            load_chunk(ci + 2, c, t, sA, thal, thal_inc, l23_fb, r_e, r_i,
                       input_proj, feedback_proj, W_ee, W_ie);
        compute(ci);
        if (ci + 1 < 23) cvt_sts(ci + 1, t, sB, smb);
        __syncthreads();
        if (ci + 1 < 23) {
            if (ci + 3 < 23)
                load_chunk(ci + 3, c, t, sB, thal, thal_inc, l23_fb, r_e, r_i,
                           input_proj, feedback_proj, W_ee, W_ie);
            compute(ci + 1);
            if (ci + 2 < 23) cvt_sts(ci + 2, t, sA, smb);
            __syncthreads();
        }
    }
    // chunk 22 computed inside the final iteration (ci == 22) — no tail call.

    // ---------------- epilogue: leaky integration + relu ----------------
    const int r0 = m0 + lm, r1 = r0 + 8;
#pragma unroll
    for (int j = 0; j < 5; j++) {
        const int col = wn * 40 + j * 8 + 2 * lc;
        const size_t i0 = ((size_t)r0 * C_ + c) * NE_ + col;
        const size_t i1 = ((size_t)r1 * C_ + c) * NE_ + col;
        float2 ev0 = *(const float2*)(e_v + i0);
        float2 ev1 = *(const float2*)(e_v + i1);
        float v0x = ev0.x + DTC * (accE[j][0] - ev0.x);
        float v0y = ev0.y + DTC * (accE[j][1] - ev0.y);
        float v1x = ev1.x + DTC * (accE[j][2] - ev1.x);
        float v1y = ev1.y + DTC * (accE[j][3] - ev1.y);
        *(float2*)(out + i0)          = make_float2(fmaxf(v0x, 0.f), fmaxf(v0y, 0.f));
        *(float2*)(out + i1)          = make_float2(fmaxf(v1x, 0.f), fmaxf(v1y, 0.f));
        *(float2*)(out + OFF_VE + i0) = make_float2(v0x, v0y);
        *(float2*)(out + OFF_VE + i1) = make_float2(v1x, v1y);
    }
    if (wn == 0) {
#pragma unroll
        for (int j = 0; j < 3; j++) {
            const int col = j * 8 + 2 * lc;
            if (col < NI_) {
                const size_t i0 = ((size_t)r0 * C_ + c) * NI_ + col;
                const size_t i1 = ((size_t)r1 * C_ + c) * NI_ + col;
                float2 iv0 = *(const float2*)(i_v + i0);
                float2 iv1 = *(const float2*)(i_v + i1);
                float v0x = iv0.x + DTC * (accI[j][0] - iv0.x);
                float v0y = iv0.y + DTC * (accI[j][1] - iv0.y);
                float v1x = iv1.x + DTC * (accI[j][2] - iv1.x);
                float v1y = iv1.y + DTC * (accI[j][3] - iv1.y);
                *(float2*)(out + OFF_RI + i0) = make_float2(fmaxf(v0x, 0.f), fmaxf(v0y, 0.f));
                *(float2*)(out + OFF_RI + i1) = make_float2(fmaxf(v1x, 0.f), fmaxf(v1y, 0.f));
                *(float2*)(out + OFF_VI + i0) = make_float2(v0x, v0y);
                *(float2*)(out + OFF_VI + i1) = make_float2(v1x, v1y);
            }
        }
    }
}

extern "C" void kernel_launch(void* const* d_in, const int* in_sizes, int n_in,
                              void* d_out, int out_size) {
    (void)in_sizes; (void)n_in; (void)out_size;
    cudaFuncSetAttribute(ei_ldsm, cudaFuncAttributeMaxDynamicSharedMemorySize,
                         SMEM_BYTES);
    ei_ldsm<<<C_, 256, SMEM_BYTES>>>(
        (const float*)d_in[0],   // thal
        (const float*)d_in[1],   // thal_increments
        (const float*)d_in[2],   // l23_fb
        (const float*)d_in[3],   // r_e
        (const float*)d_in[4],   // r_i
        (const float*)d_in[5],   // e_v
        (const float*)d_in[6],   // i_v
        (const float*)d_in[7],   // input_proj
        (const float*)d_in[8],   // feedback_proj
        (const float*)d_in[9],   // W_ee
        (const float*)d_in[10],  // W_ei
        (const float*)d_in[11],  // W_ie
        (float*)d_out);
}